// round 4
// baseline (speedup 1.0000x reference)
#include <cuda_runtime.h>
#include <cstdint>

// Problem constants
#define NN    32
#define CIN   64
#define COUTC 64
#define REDC  2
#define TT    64
#define VV    128
#define KK    (REDC*TT)   // 128
#define KC    16          // k-chunk for kB

typedef unsigned long long ull;

// Scratch (device globals; no allocation allowed)
__device__ float g_xf[NN*COUTC*TT*VV];      // [n][o][t][v]  67 MB
__device__ float g_a [NN*KK*VV];            // [n][k][v]      2 MB
__device__ float g_b [NN*KK*VV];            // [n][k][w]      2 MB
__device__ float g_xm[(size_t)NN*TT*VV*VV]; // [n][t][v][w] 134 MB

// ---- packed f32x2 helpers (FFMA2) -----------------------------------------
__device__ __forceinline__ ull pack2(float lo, float hi) {
    ull r;
    asm("mov.b64 %0, {%1, %2};" : "=l"(r) : "f"(lo), "f"(hi));
    return r;
}
__device__ __forceinline__ void unpack2(ull p, float& lo, float& hi) {
    asm("mov.b64 {%0, %1}, %2;" : "=f"(lo), "=f"(hi) : "l"(p));
}
__device__ __forceinline__ void ffma2(ull& acc, ull a, ull b) {
    asm("fma.rn.f32x2 %0, %1, %2, %0;" : "+l"(acc) : "l"(a), "l"(b));
}
__device__ __forceinline__ float hsum2(ull p) {
    float lo, hi; unpack2(p, lo, hi); return lo + hi;
}

// tanh(x) = 1 - 2/(1+e^{2x}) via MUFU.EX2 + MUFU.RCP (abs err ~1e-6)
__device__ __forceinline__ float fast_tanh(float x) {
    float e;
    asm("ex2.approx.f32 %0, %1;" : "=f"(e) : "f"(x * 2.885390081777927f));
    float r;
    asm("rcp.approx.f32 %0, %1;" : "=f"(r) : "f"(e + 1.0f));
    return 1.0f - 2.0f * r;
}

// ---------------------------------------------------------------------------
// kA: per (n,t): thread v holds x[n,:,t,v]; 1x1 convs -> xf, a, b.
// xf main GEMM uses FFMA2 paired over c (Wf kept in native [o][c] layout).
// ---------------------------------------------------------------------------
__global__ void __launch_bounds__(128) kA(
    const float* __restrict__ x,
    const float* __restrict__ Wf,  const float* __restrict__ bf,
    const float* __restrict__ Wm1, const float* __restrict__ bm1,
    const float* __restrict__ Wm2, const float* __restrict__ bm2)
{
    __shared__ float Wfs[COUTC*CIN];   // [o][c] native layout, 16KB
    __shared__ float w1s[REDC*CIN];
    __shared__ float w2s[REDC*CIN];

    const int tid = threadIdx.x;
    const int t = blockIdx.x;
    const int n = blockIdx.y;

    for (int e = tid; e < COUTC*CIN; e += 128) Wfs[e] = Wf[e];
    for (int e = tid; e < REDC*CIN; e += 128) { w1s[e] = Wm1[e]; w2s[e] = Wm2[e]; }
    __syncthreads();

    const int v = tid;
    const float* xp = x + ((size_t)n*CIN*TT + t)*VV + v;
    float xv[CIN];
    #pragma unroll
    for (int c = 0; c < CIN; c++) xv[c] = xp[(size_t)c*TT*VV];

    // small 1x1 convs -> a, b (scalar, tiny)
    #pragma unroll
    for (int r = 0; r < REDC; r++) {
        float s1 = bm1[r], s2 = bm2[r];
        #pragma unroll
        for (int c = 0; c < CIN; c++) {
            s1 += w1s[r*CIN + c] * xv[c];
            s2 += w2s[r*CIN + c] * xv[c];
        }
        size_t idx = ((size_t)n*KK + r*TT + t)*VV + v;
        g_a[idx] = s1;
        g_b[idx] = s2;
    }

    // pack x into f32x2 pairs over c
    ull xp2[CIN/2];
    #pragma unroll
    for (int c2 = 0; c2 < CIN/2; c2++) xp2[c2] = pack2(xv[2*c2], xv[2*c2+1]);

    // xf GEMM: per o, 32 FFMA2 paired over c
    #pragma unroll 1
    for (int o = 0; o < COUTC; o++) {
        ull acc = 0ULL;
        const ull* wp = (const ull*)&Wfs[o*CIN];
        #pragma unroll
        for (int c2 = 0; c2 < CIN/2; c2++) ffma2(acc, wp[c2], xp2[c2]);
        g_xf[(((size_t)n*COUTC + o)*TT + t)*VV + v] = hsum2(acc) + bf[o];
    }
}

// ---------------------------------------------------------------------------
// kB: xm[n,t,v,w] = brm[t] + A[t,v,w] + sum_k Wrm[t][k]*tanh(a[n,k,v]-b[n,k,w])
// Block: one n, 2 v's, 64 w's (vw tile 128), all 64 t.
// Thread: 8t x 4vw outputs, FFMA2 paired over k (acc.lo even-k, acc.hi odd-k).
// smem: Wrm native [t][k] 32KB + b slice [k][64w] 32KB + a slice [k][2v] 1KB
//       + ds [8 kpair][128 vw][2] 8KB  => 74752 B dynamic
// ---------------------------------------------------------------------------
__global__ void __launch_bounds__(256) kB(
    const float* __restrict__ Wrm,
    const float* __restrict__ A, const float* __restrict__ brm)
{
    extern __shared__ float sm[];
    float* WTs = sm;             // [64t][128k]
    float* bsm = WTs + TT*KK;    // [128k][64w]
    float* ash = bsm + KK*64;    // [128k][2v]
    float* ds  = ash + KK*2;     // [8][128][2]

    const int tid = threadIdx.x;
    const int n  = blockIdx.z;
    const int v0 = blockIdx.y * 2;
    const int w0 = blockIdx.x * 64;

    for (int e = tid; e < TT*KK; e += 256) WTs[e] = Wrm[e];
    for (int e = tid; e < KK*64; e += 256) {
        int k = e >> 6, w = e & 63;
        bsm[e] = g_b[((size_t)n*KK + k)*VV + w0 + w];
    }
    {
        int e = tid;   // 256 entries exactly
        int k = e >> 1, vl = e & 1;
        ash[e] = g_a[((size_t)n*KK + k)*VV + v0 + vl];
    }

    // GEMM-phase mapping: warp -> t-group, lane -> vw stripe
    const int tg  = tid >> 5;          // 0..7 : t = tg*8 + ti
    const int vwg = tid & 31;          // vw = vwg + 32*j, j=0..3

    // tanh-phase mapping: thread owns one vw and 4 k-pairs
    const int tvw = tid & 127;
    const int tv  = tvw >> 6;          // 0..1
    const int tw  = tvw & 63;
    const int kpb = (tid >> 7) * 4;    // 0 or 4

    ull acc2[8][4];
    #pragma unroll
    for (int i = 0; i < 8; i++)
        #pragma unroll
        for (int j = 0; j < 4; j++) acc2[i][j] = 0ULL;

    for (int k0 = 0; k0 < KK; k0 += KC) {
        __syncthreads();   // ds consumed by previous GEMM phase (covers init loads too)
        #pragma unroll
        for (int kp = 0; kp < 4; kp++) {
            const int k = k0 + (kpb + kp)*2;
            float d0 = fast_tanh(ash[k*2 + tv]     - bsm[k*64 + tw]);
            float d1 = fast_tanh(ash[(k+1)*2 + tv] - bsm[(k+1)*64 + tw]);
            *(ull*)&ds[((kpb + kp)*128 + tvw)*2] = pack2(d0, d1);
        }
        __syncthreads();

        #pragma unroll
        for (int kp = 0; kp < 8; kp++) {
            ull W2[8], D2[4];
            #pragma unroll
            for (int ti = 0; ti < 8; ti++)    // warp-uniform LDS64
                W2[ti] = *(const ull*)&WTs[(tg*8 + ti)*KK + k0 + kp*2];
            #pragma unroll
            for (int j = 0; j < 4; j++)       // lane-consecutive LDS64
                D2[j] = *(const ull*)&ds[(kp*128 + vwg + 32*j)*2];
            #pragma unroll
            for (int ti = 0; ti < 8; ti++)
                #pragma unroll
                for (int j = 0; j < 4; j++)
                    ffma2(acc2[ti][j], W2[ti], D2[j]);
        }
    }

    // Epilogue: vw = vwg + 32j -> v = j>>1, w = vwg + 32*(j&1)
    #pragma unroll
    for (int ti = 0; ti < 8; ti++) {
        const int t = tg*8 + ti;
        const float bt = __ldg(&brm[t]);
        #pragma unroll
        for (int j = 0; j < 4; j++) {
            const int v = v0 + (j >> 1);
            const int w = w0 + vwg + 32*(j & 1);
            float s = hsum2(acc2[ti][j]) + bt + A[((size_t)t*VV + v)*VV + w];
            g_xm[(((size_t)n*TT + t)*VV + v)*VV + w] = s;
        }
    }
}

// ---------------------------------------------------------------------------
// kC: out[n,c,t,w] = sum_v xf[n,c,t,v] * xm[n,t,v,w]
// Block: one (n,t): 64c x 128w, K=v chunked by 32, FFMA2 paired over v.
// xms staged transposed [w][kk] (pad 34) so v-pairs are contiguous.
// ---------------------------------------------------------------------------
#define XMP 34
__global__ void __launch_bounds__(256) kC(float* __restrict__ out) {
    __shared__ float xfs[COUTC*32];    // [c][kk]   8KB
    __shared__ float xms[VV*XMP];      // [w][kk]  17KB

    const int tid = threadIdx.x;
    const int t = blockIdx.x;
    const int n = blockIdx.y;
    const int tx = tid & 31;   // w = tx + 32*j
    const int ty = tid >> 5;   // c = ty*8 + ci

    ull acc2[8][4];
    #pragma unroll
    for (int i = 0; i < 8; i++)
        #pragma unroll
        for (int j = 0; j < 4; j++) acc2[i][j] = 0ULL;

    for (int v0 = 0; v0 < VV; v0 += 32) {
        __syncthreads();
        for (int e = tid; e < COUTC*32; e += 256) {
            int kk = e & 31, c = e >> 5;
            xfs[e] = g_xf[(((size_t)n*COUTC + c)*TT + t)*VV + v0 + kk];
        }
        for (int e = tid; e < 32*VV; e += 256) {
            int w = e & 127, kk = e >> 7;           // coalesced read, transposed store
            xms[w*XMP + kk] = g_xm[(((size_t)n*TT + t)*VV + v0 + kk)*VV + w];
        }
        __syncthreads();

        #pragma unroll
        for (int kk2 = 0; kk2 < 16; kk2++) {
            ull xf2[8], xm2[4];
            #pragma unroll
            for (int ci = 0; ci < 8; ci++)   // warp-uniform LDS64
                xf2[ci] = *(const ull*)&xfs[(ty*8 + ci)*32 + kk2*2];
            #pragma unroll
            for (int j = 0; j < 4; j++)      // lane stride 136B -> 2-way max
                xm2[j] = *(const ull*)&xms[(tx + 32*j)*XMP + kk2*2];
            #pragma unroll
            for (int ci = 0; ci < 8; ci++)
                #pragma unroll
                for (int j = 0; j < 4; j++)
                    ffma2(acc2[ci][j], xf2[ci], xm2[j]);
        }
    }

    #pragma unroll
    for (int ci = 0; ci < 8; ci++) {
        const int c = ty*8 + ci;
        #pragma unroll
        for (int j = 0; j < 4; j++) {
            out[(((size_t)n*COUTC + c)*TT + t)*VV + tx + 32*j] = hsum2(acc2[ci][j]);
        }
    }
}

// ---------------------------------------------------------------------------
extern "C" void kernel_launch(void* const* d_in, const int* in_sizes, int n_in,
                              void* d_out, int out_size)
{
    const float* x   = (const float*)d_in[0];
    const float* A   = (const float*)d_in[1];
    const float* Wf  = (const float*)d_in[2];
    const float* bf  = (const float*)d_in[3];
    const float* Wm1 = (const float*)d_in[4];
    const float* bm1 = (const float*)d_in[5];
    const float* Wm2 = (const float*)d_in[6];
    const float* bm2 = (const float*)d_in[7];
    const float* Wrm = (const float*)d_in[8];
    const float* brm = (const float*)d_in[9];
    float* out = (float*)d_out;

    const int kb_smem = (TT*KK + KK*64 + KK*2 + 8*128*2) * (int)sizeof(float); // 74752
    static int kb_smem_set = 0;
    if (!kb_smem_set) {
        cudaFuncSetAttribute(kB, cudaFuncAttributeMaxDynamicSharedMemorySize, kb_smem);
        kb_smem_set = 1;
    }

    kA<<<dim3(TT, NN), 128>>>(x, Wf, bf, Wm1, bm1, Wm2, bm2);
    kB<<<dim3(VV/64, VV/2, NN), 256, kb_smem>>>(Wrm, A, brm);
    kC<<<dim3(TT, NN), 256>>>(out);
}

// round 5
// speedup vs baseline: 1.0673x; 1.0673x over previous
#include <cuda_runtime.h>
#include <cstdint>

// Problem constants
#define NN    32
#define CIN   64
#define COUTC 64
#define REDC  2
#define TT    64
#define VV    128
#define KK    (REDC*TT)   // 128

typedef unsigned int uint32;
typedef unsigned long long ull;

// Scratch (device globals; no allocation allowed)
__device__ float g_xf[NN*COUTC*TT*VV];      // [n][o][t][v]  67 MB
__device__ float g_a [NN*KK*VV];            // [n][k][v]      2 MB
__device__ float g_b [NN*KK*VV];            // [n][k][w]      2 MB
__device__ float g_xm[(size_t)NN*TT*VV*VV]; // [n][t][v][w] 134 MB
__device__ float g_WrmF[4*16*32*4];         // tf32 A-fragments [mg][kt][lane][4]

// tanh(x) = 1 - 2/(1+e^{2x}) via MUFU.EX2 + MUFU.RCP (abs err ~1e-6)
__device__ __forceinline__ float fast_tanh(float x) {
    float e;
    asm("ex2.approx.f32 %0, %1;" : "=f"(e) : "f"(x * 2.885390081777927f));
    float r;
    asm("rcp.approx.f32 %0, %1;" : "=f"(r) : "f"(e + 1.0f));
    return 1.0f - 2.0f * r;
}

__device__ __forceinline__ uint32 to_tf32(float x) {
    uint32 u;
    asm("cvt.rna.tf32.f32 %0, %1;" : "=r"(u) : "f"(x));
    return u;
}

__device__ __forceinline__ void mma_tf32(
    float& c0, float& c1, float& c2, float& c3,
    uint32 a0, uint32 a1, uint32 a2, uint32 a3,
    uint32 b0, uint32 b1)
{
    asm volatile(
        "mma.sync.aligned.m16n8k8.row.col.f32.tf32.tf32.f32 "
        "{%0,%1,%2,%3}, {%4,%5,%6,%7}, {%8,%9}, {%0,%1,%2,%3};"
        : "+f"(c0), "+f"(c1), "+f"(c2), "+f"(c3)
        : "r"(a0), "r"(a1), "r"(a2), "r"(a3), "r"(b0), "r"(b1));
}

// ---------------------------------------------------------------------------
// kP: build tf32 A-fragments of Wrm for mma.m16n8k8.
// a0=(r,c) a1=(r+8,c) a2=(r,c+4) a3=(r+8,c+4), r=mg*16+lane/4, c=kt*8+lane%4
// ---------------------------------------------------------------------------
__global__ void kP(const float* __restrict__ Wrm) {
    int idx = blockIdx.x * blockDim.x + threadIdx.x;   // 2048
    if (idx >= 2048) return;
    int lane = idx & 31, kt = (idx >> 5) & 15, mg = idx >> 9;
    int grp = lane >> 2, tig = lane & 3;
    int r0 = mg*16 + grp, r1 = r0 + 8;
    int c0 = kt*8 + tig, c1 = c0 + 4;
    uint32 q0 = to_tf32(Wrm[r0*KK + c0]);
    uint32 q1 = to_tf32(Wrm[r1*KK + c0]);
    uint32 q2 = to_tf32(Wrm[r0*KK + c1]);
    uint32 q3 = to_tf32(Wrm[r1*KK + c1]);
    float4 f;
    f.x = __uint_as_float(q0); f.y = __uint_as_float(q1);
    f.z = __uint_as_float(q2); f.w = __uint_as_float(q3);
    *(float4*)&g_WrmF[idx*4] = f;
}

// ---------------------------------------------------------------------------
// kA (R2 version): per (n,t): thread v holds x[n,:,t,v]; -> xf, a, b.
// ---------------------------------------------------------------------------
__global__ void __launch_bounds__(128) kA(
    const float* __restrict__ x,
    const float* __restrict__ Wf,  const float* __restrict__ bf,
    const float* __restrict__ Wm1, const float* __restrict__ bm1,
    const float* __restrict__ Wm2, const float* __restrict__ bm2)
{
    __shared__ float WfT[CIN*68];
    __shared__ float w1s[REDC*CIN];
    __shared__ float w2s[REDC*CIN];

    const int tid = threadIdx.x;
    const int t = blockIdx.x;
    const int n = blockIdx.y;

    for (int e = tid; e < COUTC*CIN; e += 128) {
        int o = e & 63, c = e >> 6;
        WfT[c*68 + o] = Wf[o*CIN + c];
    }
    for (int e = tid; e < REDC*CIN; e += 128) { w1s[e] = Wm1[e]; w2s[e] = Wm2[e]; }
    __syncthreads();

    const int v = tid;
    const float* xp = x + ((size_t)n*CIN*TT + t)*VV + v;
    float xv[CIN];
    #pragma unroll
    for (int c = 0; c < CIN; c++) xv[c] = xp[(size_t)c*TT*VV];

    #pragma unroll
    for (int r = 0; r < REDC; r++) {
        float s1 = bm1[r], s2 = bm2[r];
        #pragma unroll
        for (int c = 0; c < CIN; c++) {
            s1 += w1s[r*CIN + c] * xv[c];
            s2 += w2s[r*CIN + c] * xv[c];
        }
        size_t idx = ((size_t)n*KK + r*TT + t)*VV + v;
        g_a[idx] = s1;
        g_b[idx] = s2;
    }

    #pragma unroll 1
    for (int o0 = 0; o0 < COUTC; o0 += 4) {
        float a0 = bf[o0], a1 = bf[o0+1], a2 = bf[o0+2], a3 = bf[o0+3];
        #pragma unroll
        for (int c = 0; c < CIN; c++) {
            float4 wv = *(const float4*)&WfT[c*68 + o0];
            a0 += wv.x * xv[c];
            a1 += wv.y * xv[c];
            a2 += wv.z * xv[c];
            a3 += wv.w * xv[c];
        }
        size_t base = (((size_t)n*COUTC + o0)*TT + t)*VV + v;
        g_xf[base]              = a0;
        g_xf[base + TT*VV]      = a1;
        g_xf[base + 2*TT*VV]    = a2;
        g_xf[base + 3*TT*VV]    = a3;
    }
}

// ---------------------------------------------------------------------------
// kB (tf32 mma): xm[n,t,v,w] = brm[t] + A[t,v,w] + sum_k Wrm[t,k]*tanh(a-b)
// Block: one n, 2 v rows (=256 vw, w full). M=64 t, K=128, N=256 local.
// Per 8-k step: tanh tile -> ds (fragment-swizzled), then 8 warps x 16 HMMA.
// smem: b[n] full 64KB + a slice 1KB + WrmF 32KB + ds[256][10] 10KB = 107KB
// ---------------------------------------------------------------------------
#define DSP 10
__global__ void __launch_bounds__(256) kB(
    const float* __restrict__ A, const float* __restrict__ brm)
{
    extern __shared__ float sm[];
    float* bsm = sm;                 // [128k][128w]
    float* ash = bsm + KK*VV;        // [128k][2v]
    float* wfs = ash + KK*2;         // [4][16][32][4] A-fragments
    float* ds  = wfs + 8192;         // [256 vw][10] (cols 0..7 used)

    const int tid = threadIdx.x;
    const int n  = blockIdx.y;
    const int v0 = blockIdx.x * 2;

    for (int e = tid; e < KK*VV; e += 256) bsm[e] = g_b[(size_t)n*KK*VV + e];
    ash[tid] = g_a[((size_t)n*KK + (tid >> 1))*VV + v0 + (tid & 1)];
    for (int e = tid; e < 8192; e += 256) wfs[e] = g_WrmF[e];

    const int warp = tid >> 5, lane = tid & 31;
    const int grp = lane >> 2, tig = lane & 3;
    const int mg = warp & 3;            // t group: t0 = mg*16
    const int nb = (warp >> 2) * 128;   // local n base (0 or 128)

    // tanh-phase mapping: thread owns vw = tid (v = tid>>7, w = tid&127)
    const int tv = tid >> 7, tw = tid & 127;

    float acc[16][4];
    #pragma unroll
    for (int i = 0; i < 16; i++)
        #pragma unroll
        for (int j = 0; j < 4; j++) acc[i][j] = 0.0f;

    #pragma unroll 1
    for (int ks = 0; ks < 16; ks++) {
        const int k0 = ks * 8;
        __syncthreads();   // previous GEMM done with ds (first iter: staging done)
        #pragma unroll
        for (int j = 0; j < 4; j++) {
            float d0 = fast_tanh(ash[(k0+j)*2 + tv]   - bsm[(k0+j)*VV + tw]);
            float d1 = fast_tanh(ash[(k0+j+4)*2 + tv] - bsm[(k0+j+4)*VV + tw]);
            uint32 u0 = to_tf32(d0), u1 = to_tf32(d1);
            ull p;
            asm("mov.b64 %0, {%1, %2};" : "=l"(p) : "r"(u0), "r"(u1));
            *(ull*)&ds[tid*DSP + 2*j] = p;   // pos 2j: k0+j, pos 2j+1: k0+j+4
        }
        __syncthreads();

        float4 af = *(const float4*)&wfs[((mg*16 + ks)*32 + lane)*4];
        uint32 a0 = __float_as_uint(af.x), a1 = __float_as_uint(af.y);
        uint32 a2 = __float_as_uint(af.z), a3 = __float_as_uint(af.w);

        #pragma unroll
        for (int tt = 0; tt < 16; tt++) {
            const int col = nb + tt*8 + grp;
            ull p = *(const ull*)&ds[col*DSP + 2*tig];
            uint32 b0 = (uint32)p, b1 = (uint32)(p >> 32);
            mma_tf32(acc[tt][0], acc[tt][1], acc[tt][2], acc[tt][3],
                     a0, a1, a2, a3, b0, b1);
        }
    }

    // Epilogue: c0,c1 -> (t_lo, w, w+1); c2,c3 -> (t_hi, w, w+1)
    const int t_lo = mg*16 + grp, t_hi = t_lo + 8;
    const float bt0 = __ldg(&brm[t_lo]);
    const float bt1 = __ldg(&brm[t_hi]);
    #pragma unroll
    for (int tt = 0; tt < 16; tt++) {
        const int vwl = nb + tt*8 + 2*tig;
        const int v = v0 + (vwl >> 7);
        const int w = vwl & 127;
        float2 A0 = *(const float2*)&A[((size_t)t_lo*VV + v)*VV + w];
        float2 A1 = *(const float2*)&A[((size_t)t_hi*VV + v)*VV + w];
        float2 r0, r1;
        r0.x = acc[tt][0] + bt0 + A0.x;  r0.y = acc[tt][1] + bt0 + A0.y;
        r1.x = acc[tt][2] + bt1 + A1.x;  r1.y = acc[tt][3] + bt1 + A1.y;
        *(float2*)&g_xm[(((size_t)n*TT + t_lo)*VV + v)*VV + w] = r0;
        *(float2*)&g_xm[(((size_t)n*TT + t_hi)*VV + v)*VV + w] = r1;
    }
}

// ---------------------------------------------------------------------------
// kC (R2 version): out[n,c,t,w] = sum_v xf[n,c,t,v] * xm[n,t,v,w]
// ---------------------------------------------------------------------------
__global__ void __launch_bounds__(256) kC(float* __restrict__ out) {
    __shared__ float xfs[COUTC*32];
    __shared__ float xms[32*VV];

    const int tid = threadIdx.x;
    const int t = blockIdx.x;
    const int n = blockIdx.y;
    const int tx = tid & 31;
    const int ty = tid >> 5;

    float acc[8][4];
    #pragma unroll
    for (int i = 0; i < 8; i++)
        #pragma unroll
        for (int j = 0; j < 4; j++) acc[i][j] = 0.0f;

    for (int v0 = 0; v0 < VV; v0 += 32) {
        __syncthreads();
        for (int e = tid; e < COUTC*32; e += 256) {
            int kk = e & 31, c = e >> 5;
            xfs[e] = g_xf[(((size_t)n*COUTC + c)*TT + t)*VV + v0 + kk];
        }
        for (int e = tid; e < 32*VV; e += 256) {
            int w = e & 127, kk = e >> 7;
            xms[e] = g_xm[(((size_t)n*TT + t)*VV + v0 + kk)*VV + w];
        }
        __syncthreads();

        #pragma unroll
        for (int kk4 = 0; kk4 < 8; kk4++) {
            float xfr[8][4];
            #pragma unroll
            for (int ci = 0; ci < 8; ci++) {
                float4 f = *(const float4*)&xfs[(ty*8 + ci)*32 + kk4*4];
                xfr[ci][0] = f.x; xfr[ci][1] = f.y; xfr[ci][2] = f.z; xfr[ci][3] = f.w;
            }
            float xmr[4][4];
            #pragma unroll
            for (int j = 0; j < 4; j++) {
                float4 m = *(const float4*)&xms[(kk4*4 + j)*VV + tx*4];
                xmr[j][0] = m.x; xmr[j][1] = m.y; xmr[j][2] = m.z; xmr[j][3] = m.w;
            }
            #pragma unroll
            for (int j = 0; j < 4; j++)
                #pragma unroll
                for (int ci = 0; ci < 8; ci++) {
                    acc[ci][0] += xfr[ci][j] * xmr[j][0];
                    acc[ci][1] += xfr[ci][j] * xmr[j][1];
                    acc[ci][2] += xfr[ci][j] * xmr[j][2];
                    acc[ci][3] += xfr[ci][j] * xmr[j][3];
                }
        }
    }

    #pragma unroll
    for (int ci = 0; ci < 8; ci++) {
        int c = ty*8 + ci;
        float4 r = make_float4(acc[ci][0], acc[ci][1], acc[ci][2], acc[ci][3]);
        *(float4*)&out[(((size_t)n*COUTC + c)*TT + t)*VV + tx*4] = r;
    }
}

// ---------------------------------------------------------------------------
extern "C" void kernel_launch(void* const* d_in, const int* in_sizes, int n_in,
                              void* d_out, int out_size)
{
    const float* x   = (const float*)d_in[0];
    const float* A   = (const float*)d_in[1];
    const float* Wf  = (const float*)d_in[2];
    const float* bf  = (const float*)d_in[3];
    const float* Wm1 = (const float*)d_in[4];
    const float* bm1 = (const float*)d_in[5];
    const float* Wm2 = (const float*)d_in[6];
    const float* bm2 = (const float*)d_in[7];
    const float* Wrm = (const float*)d_in[8];
    const float* brm = (const float*)d_in[9];
    float* out = (float*)d_out;

    const int kb_smem = (KK*VV + KK*2 + 8192 + 256*DSP) * (int)sizeof(float); // 109568
    static int attr_set = 0;
    if (!attr_set) {
        cudaFuncSetAttribute(kB, cudaFuncAttributeMaxDynamicSharedMemorySize, kb_smem);
        attr_set = 1;
    }

    kP<<<8, 256>>>(Wrm);
    kA<<<dim3(TT, NN), 128>>>(x, Wf, bf, Wm1, bm1, Wm2, bm2);
    kB<<<dim3(VV/2, NN), 256, kb_smem>>>(A, brm);
    kC<<<dim3(TT, NN), 256>>>(out);
}

// round 6
// speedup vs baseline: 1.3782x; 1.2913x over previous
#include <cuda_runtime.h>
#include <cstdint>

// Problem constants
#define NN    32
#define CIN   64
#define COUTC 64
#define REDC  2
#define TT    64
#define VV    128
#define KK    (REDC*TT)   // 128

typedef unsigned int uint32;

// Scratch (device globals; no allocation allowed)
__device__ float g_xf[NN*COUTC*TT*VV];      // [n][o][t][v]  67 MB
__device__ float g_a [NN*KK*VV];            // [n][k][v]      2 MB
__device__ float g_b [NN*KK*VV];            // [n][k][w]      2 MB
__device__ float g_xm[(size_t)NN*TT*VV*VV]; // [n][t][v][w] 134 MB
__device__ float g_WrmF[4*16*32*4];         // tf32 A-fragments [mg][kt][lane][4]

// tanh(x) = 1 - 2/(1+e^{2x}) via MUFU.EX2 + MUFU.RCP (abs err ~1e-6)
__device__ __forceinline__ float fast_tanh(float x) {
    float e;
    asm("ex2.approx.f32 %0, %1;" : "=f"(e) : "f"(x * 2.885390081777927f));
    float r;
    asm("rcp.approx.f32 %0, %1;" : "=f"(r) : "f"(e + 1.0f));
    return 1.0f - 2.0f * r;
}

__device__ __forceinline__ uint32 to_tf32(float x) {
    uint32 u;
    asm("cvt.rna.tf32.f32 %0, %1;" : "=r"(u) : "f"(x));
    return u;
}
__device__ __forceinline__ float tf32f(float x) {
    return __uint_as_float(to_tf32(x));
}

__device__ __forceinline__ void mma_tf32(
    float* c,
    uint32 a0, uint32 a1, uint32 a2, uint32 a3,
    uint32 b0, uint32 b1)
{
    asm volatile(
        "mma.sync.aligned.m16n8k8.row.col.f32.tf32.tf32.f32 "
        "{%0,%1,%2,%3}, {%4,%5,%6,%7}, {%8,%9}, {%0,%1,%2,%3};"
        : "+f"(c[0]), "+f"(c[1]), "+f"(c[2]), "+f"(c[3])
        : "r"(a0), "r"(a1), "r"(a2), "r"(a3), "r"(b0), "r"(b1));
}

// ---------------------------------------------------------------------------
// kP: build tf32 A-fragments of Wrm for mma.m16n8k8.
// ---------------------------------------------------------------------------
__global__ void kP(const float* __restrict__ Wrm) {
    int idx = blockIdx.x * blockDim.x + threadIdx.x;   // 2048
    if (idx >= 2048) return;
    int lane = idx & 31, kt = (idx >> 5) & 15, mg = idx >> 9;
    int grp = lane >> 2, tig = lane & 3;
    int r0 = mg*16 + grp, r1 = r0 + 8;
    int c0 = kt*8 + tig, c1 = c0 + 4;
    float4 f;
    f.x = tf32f(Wrm[r0*KK + c0]);
    f.y = tf32f(Wrm[r1*KK + c0]);
    f.z = tf32f(Wrm[r0*KK + c1]);
    f.w = tf32f(Wrm[r1*KK + c1]);
    *(float4*)&g_WrmF[idx*4] = f;
}

// ---------------------------------------------------------------------------
// kA: per (n,t): thread v holds x[n,:,t,v]; -> xf, a, b.
// ---------------------------------------------------------------------------
__global__ void __launch_bounds__(128) kA(
    const float* __restrict__ x,
    const float* __restrict__ Wf,  const float* __restrict__ bf,
    const float* __restrict__ Wm1, const float* __restrict__ bm1,
    const float* __restrict__ Wm2, const float* __restrict__ bm2)
{
    __shared__ float WfT[CIN*68];
    __shared__ float w1s[REDC*CIN];
    __shared__ float w2s[REDC*CIN];

    const int tid = threadIdx.x;
    const int t = blockIdx.x;
    const int n = blockIdx.y;

    for (int e = tid; e < COUTC*CIN; e += 128) {
        int o = e & 63, c = e >> 6;
        WfT[c*68 + o] = Wf[o*CIN + c];
    }
    for (int e = tid; e < REDC*CIN; e += 128) { w1s[e] = Wm1[e]; w2s[e] = Wm2[e]; }
    __syncthreads();

    const int v = tid;
    const float* xp = x + ((size_t)n*CIN*TT + t)*VV + v;
    float xv[CIN];
    #pragma unroll
    for (int c = 0; c < CIN; c++) xv[c] = xp[(size_t)c*TT*VV];

    #pragma unroll
    for (int r = 0; r < REDC; r++) {
        float s1 = bm1[r], s2 = bm2[r];
        #pragma unroll
        for (int c = 0; c < CIN; c++) {
            s1 += w1s[r*CIN + c] * xv[c];
            s2 += w2s[r*CIN + c] * xv[c];
        }
        size_t idx = ((size_t)n*KK + r*TT + t)*VV + v;
        g_a[idx] = s1;
        g_b[idx] = s2;
    }

    #pragma unroll 1
    for (int o0 = 0; o0 < COUTC; o0 += 4) {
        float a0 = bf[o0], a1 = bf[o0+1], a2 = bf[o0+2], a3 = bf[o0+3];
        #pragma unroll
        for (int c = 0; c < CIN; c++) {
            float4 wv = *(const float4*)&WfT[c*68 + o0];
            a0 += wv.x * xv[c];
            a1 += wv.y * xv[c];
            a2 += wv.z * xv[c];
            a3 += wv.w * xv[c];
        }
        size_t base = (((size_t)n*COUTC + o0)*TT + t)*VV + v;
        g_xf[base]              = a0;
        g_xf[base + TT*VV]      = a1;
        g_xf[base + 2*TT*VV]    = a2;
        g_xf[base + 3*TT*VV]    = a3;
    }
}

// ---------------------------------------------------------------------------
// kB: xm[n,t,v,w] = brm[t] + A[t,v,w] + sum_k Wrm[t,k]*tanh(a[n,k,v]-b[n,k,w])
// Block: one n, 2 v rows (256 local cols). Warp owns 32 cols x all 64 t.
// tanh computed inline in B-fragment register layout; no inner barriers.
// smem: bsm [128k][136] + ash [128k][2] + wfs 32KB = 101 KB
// ---------------------------------------------------------------------------
#define BSMP 136
__global__ void __launch_bounds__(256, 2) kB(
    const float* __restrict__ A, const float* __restrict__ brm)
{
    extern __shared__ float sm[];
    float* bsm = sm;                // [128][136]
    float* ash = bsm + KK*BSMP;     // [128][2]
    float* wfs = ash + KK*2;        // [4][16][32][4]

    const int tid = threadIdx.x;
    const int n  = blockIdx.y;
    const int v0 = blockIdx.x * 2;

    for (int e = tid; e < KK*VV; e += 256) {
        int k = e >> 7, w = e & 127;
        bsm[k*BSMP + w] = g_b[(size_t)n*KK*VV + e];
    }
    ash[tid] = g_a[((size_t)n*KK + (tid >> 1))*VV + v0 + (tid & 1)];
    for (int e = tid; e < 8192; e += 256) wfs[e] = g_WrmF[e];
    __syncthreads();

    const int warp = tid >> 5, lane = tid & 31;
    const int grp = lane >> 2, tig = lane & 3;
    const int vbit = warp >> 2;          // 0/1 -> v = v0 + vbit
    const int cb = (warp & 3) * 32;      // w base for this warp

    int wc0 = cb + grp;                  // j stride 8

    float acc[4][4][4];                  // [mg][j][4]
    #pragma unroll
    for (int m = 0; m < 4; m++)
        #pragma unroll
        for (int j = 0; j < 4; j++)
            #pragma unroll
            for (int q = 0; q < 4; q++) acc[m][j][q] = 0.0f;

    #pragma unroll 1
    for (int ks = 0; ks < 16; ks++) {
        const int k0 = ks * 8;
        const float a_lo = ash[(k0 + tig)*2 + vbit];
        const float a_hi = ash[(k0 + tig + 4)*2 + vbit];

        uint32 af[4][4];
        #pragma unroll
        for (int mg = 0; mg < 4; mg++) {
            float4 f = *(const float4*)&wfs[((mg*16 + ks)*32 + lane)*4];
            af[mg][0] = __float_as_uint(f.x);
            af[mg][1] = __float_as_uint(f.y);
            af[mg][2] = __float_as_uint(f.z);
            af[mg][3] = __float_as_uint(f.w);
        }

        const float* blo = &bsm[(k0 + tig)*BSMP];
        const float* bhi = &bsm[(k0 + tig + 4)*BSMP];
        #pragma unroll
        for (int j = 0; j < 4; j++) {
            const int wcj = wc0 + j*8;
            uint32 u0 = to_tf32(fast_tanh(a_lo - blo[wcj]));
            uint32 u1 = to_tf32(fast_tanh(a_hi - bhi[wcj]));
            #pragma unroll
            for (int mg = 0; mg < 4; mg++)
                mma_tf32(acc[mg][j], af[mg][0], af[mg][1], af[mg][2], af[mg][3], u0, u1);
        }
    }

    // Epilogue
    const int v = v0 + vbit;
    #pragma unroll
    for (int mg = 0; mg < 4; mg++) {
        const int t_lo = mg*16 + grp, t_hi = t_lo + 8;
        const float bt0 = __ldg(&brm[t_lo]);
        const float bt1 = __ldg(&brm[t_hi]);
        #pragma unroll
        for (int j = 0; j < 4; j++) {
            const int w = cb + j*8 + 2*tig;
            float2 A0 = *(const float2*)&A[((size_t)t_lo*VV + v)*VV + w];
            float2 A1 = *(const float2*)&A[((size_t)t_hi*VV + v)*VV + w];
            float2 r0, r1;
            r0.x = acc[mg][j][0] + bt0 + A0.x;  r0.y = acc[mg][j][1] + bt0 + A0.y;
            r1.x = acc[mg][j][2] + bt1 + A1.x;  r1.y = acc[mg][j][3] + bt1 + A1.y;
            *(float2*)&g_xm[(((size_t)n*TT + t_lo)*VV + v)*VV + w] = r0;
            *(float2*)&g_xm[(((size_t)n*TT + t_hi)*VV + v)*VV + w] = r1;
        }
    }
}

// ---------------------------------------------------------------------------
// kC (tf32 mma): out[n,c,t,w] = sum_v xf[n,c,t,v] * xm[n,t,v,w]
// Block (n,t): M=64(c) N=128(w) K=128(v). Warp = 1 m-tile x 8 n-tiles.
// smem: xfs [64][132] tf32-rounded + xmt [128][132] transposed tf32.
// ---------------------------------------------------------------------------
#define XP 132
__global__ void __launch_bounds__(256, 2) kC(float* __restrict__ out) {
    extern __shared__ float sm[];
    float* xfs = sm;              // [64][132]
    float* xmt = sm + 64*XP;      // [128][132]

    const int tid = threadIdx.x;
    const int t = blockIdx.x;
    const int n = blockIdx.y;

    for (int e = tid; e < COUTC*VV; e += 256) {
        int c = e >> 7, vv = e & 127;
        xfs[c*XP + vv] = tf32f(g_xf[(((size_t)n*COUTC + c)*TT + t)*VV + vv]);
    }
    for (int e = tid; e < VV*VV; e += 256) {
        int vv = e >> 7, w = e & 127;
        xmt[w*XP + vv] = tf32f(g_xm[(((size_t)n*TT + t)*VV + vv)*VV + w]);
    }
    __syncthreads();

    const int warp = tid >> 5, lane = tid & 31;
    const int grp = lane >> 2, tig = lane & 3;
    const int mg = warp & 3;          // c tile: c0 = mg*16
    const int n0 = (warp >> 2) * 64;  // w base

    float acc[8][4];
    #pragma unroll
    for (int j = 0; j < 8; j++)
        #pragma unroll
        for (int q = 0; q < 4; q++) acc[j][q] = 0.0f;

    const int r0 = mg*16 + grp;
    #pragma unroll 1
    for (int ks = 0; ks < 16; ks++) {
        const int k0 = ks * 8;
        uint32 a0 = __float_as_uint(xfs[r0*XP + k0 + tig]);
        uint32 a1 = __float_as_uint(xfs[(r0+8)*XP + k0 + tig]);
        uint32 a2 = __float_as_uint(xfs[r0*XP + k0 + tig + 4]);
        uint32 a3 = __float_as_uint(xfs[(r0+8)*XP + k0 + tig + 4]);
        #pragma unroll
        for (int j = 0; j < 8; j++) {
            const int wcol = n0 + j*8 + grp;
            uint32 b0 = __float_as_uint(xmt[wcol*XP + k0 + tig]);
            uint32 b1 = __float_as_uint(xmt[wcol*XP + k0 + tig + 4]);
            mma_tf32(acc[j], a0, a1, a2, a3, b0, b1);
        }
    }

    const int c_lo = mg*16 + grp, c_hi = c_lo + 8;
    #pragma unroll
    for (int j = 0; j < 8; j++) {
        const int w = n0 + j*8 + 2*tig;
        *(float2*)&out[(((size_t)n*COUTC + c_lo)*TT + t)*VV + w] =
            make_float2(acc[j][0], acc[j][1]);
        *(float2*)&out[(((size_t)n*COUTC + c_hi)*TT + t)*VV + w] =
            make_float2(acc[j][2], acc[j][3]);
    }
}

// ---------------------------------------------------------------------------
extern "C" void kernel_launch(void* const* d_in, const int* in_sizes, int n_in,
                              void* d_out, int out_size)
{
    const float* x   = (const float*)d_in[0];
    const float* A   = (const float*)d_in[1];
    const float* Wf  = (const float*)d_in[2];
    const float* bf  = (const float*)d_in[3];
    const float* Wm1 = (const float*)d_in[4];
    const float* bm1 = (const float*)d_in[5];
    const float* Wm2 = (const float*)d_in[6];
    const float* bm2 = (const float*)d_in[7];
    const float* Wrm = (const float*)d_in[8];
    const float* brm = (const float*)d_in[9];
    float* out = (float*)d_out;

    const int kb_smem = (KK*BSMP + KK*2 + 8192) * (int)sizeof(float);  // 103424
    const int kc_smem = (64*XP + VV*XP) * (int)sizeof(float);          // 101376
    static int attr_set = 0;
    if (!attr_set) {
        cudaFuncSetAttribute(kB, cudaFuncAttributeMaxDynamicSharedMemorySize, kb_smem);
        cudaFuncSetAttribute(kC, cudaFuncAttributeMaxDynamicSharedMemorySize, kc_smem);
        attr_set = 1;
    }

    kP<<<8, 256>>>(Wrm);
    kA<<<dim3(TT, NN), 128>>>(x, Wf, bf, Wm1, bm1, Wm2, bm2);
    kB<<<dim3(VV/2, NN), 256, kb_smem>>>(A, brm);
    kC<<<dim3(TT, NN), 256, kc_smem>>>(out);
}

// round 9
// speedup vs baseline: 2.1037x; 1.5264x over previous
#include <cuda_runtime.h>
#include <cstdint>

// Problem constants
#define NN    32
#define CIN   64
#define COUTC 64
#define REDC  2
#define TT    64
#define VV    128
#define KK    (REDC*TT)   // 128

typedef unsigned int uint32;

// Scratch (device globals; no allocation allowed)
__device__ float g_xf[NN*COUTC*TT*VV];      // [n][o][t][v]  67 MB
__device__ float g_a [NN*KK*VV];            // [n][k][v]      2 MB
__device__ float g_b [NN*KK*VV];            // [n][k][w]      2 MB
__device__ float g_xm[(size_t)NN*TT*VV*VV]; // [n][t][v][w] 134 MB
__device__ float g_WrmF[4*16*32*4];         // tf32 A-fragments [mg][kt][lane][4]

// tanh(x) = 1 - 2/(1+e^{2x}) via MUFU.EX2 + MUFU.RCP (abs err ~1e-6)
__device__ __forceinline__ float fast_tanh(float x) {
    float e;
    asm("ex2.approx.f32 %0, %1;" : "=f"(e) : "f"(x * 2.885390081777927f));
    float r;
    asm("rcp.approx.f32 %0, %1;" : "=f"(r) : "f"(e + 1.0f));
    return 1.0f - 2.0f * r;
}

__device__ __forceinline__ uint32 to_tf32(float x) {
    uint32 u;
    asm("cvt.rna.tf32.f32 %0, %1;" : "=r"(u) : "f"(x));
    return u;
}
__device__ __forceinline__ float tf32f(float x) {
    return __uint_as_float(to_tf32(x));
}
__device__ __forceinline__ uint32 to_tf32u(float x) { return to_tf32(x); }

__device__ __forceinline__ void mma_tf32(
    float* c,
    uint32 a0, uint32 a1, uint32 a2, uint32 a3,
    uint32 b0, uint32 b1)
{
    asm volatile(
        "mma.sync.aligned.m16n8k8.row.col.f32.tf32.tf32.f32 "
        "{%0,%1,%2,%3}, {%4,%5,%6,%7}, {%8,%9}, {%0,%1,%2,%3};"
        : "+f"(c[0]), "+f"(c[1]), "+f"(c[2]), "+f"(c[3])
        : "r"(a0), "r"(a1), "r"(a2), "r"(a3), "r"(b0), "r"(b1));
}

__device__ __forceinline__ void cp_async16(void* smem_dst, const void* gmem_src) {
    uint32 d = (uint32)__cvta_generic_to_shared(smem_dst);
    asm volatile("cp.async.cg.shared.global [%0], [%1], 16;" :: "r"(d), "l"(gmem_src));
}
__device__ __forceinline__ void cp_commit() {
    asm volatile("cp.async.commit_group;");
}
template<int N>
__device__ __forceinline__ void cp_wait() {
    asm volatile("cp.async.wait_group %0;" :: "n"(N));
}

// ---------------------------------------------------------------------------
// kP: build tf32 A-fragments of Wrm for mma.m16n8k8.
// ---------------------------------------------------------------------------
__global__ void kP(const float* __restrict__ Wrm) {
    int idx = blockIdx.x * blockDim.x + threadIdx.x;   // 2048
    if (idx >= 2048) return;
    int lane = idx & 31, kt = (idx >> 5) & 15, mg = idx >> 9;
    int grp = lane >> 2, tig = lane & 3;
    int r0 = mg*16 + grp, r1 = r0 + 8;
    int c0 = kt*8 + tig, c1 = c0 + 4;
    float4 f;
    f.x = tf32f(Wrm[r0*KK + c0]);
    f.y = tf32f(Wrm[r1*KK + c0]);
    f.z = tf32f(Wrm[r0*KK + c1]);
    f.w = tf32f(Wrm[r1*KK + c1]);
    *(float4*)&g_WrmF[idx*4] = f;
}

// ---------------------------------------------------------------------------
// kA (tf32 mma): per (n,t): xf = Wf(64x64) @ X(64x128) + bf; also a,b scalar.
// smem: Xs [64c][136] (X k-major for B-frags) + Wfs [64o][68] + wms [4][64]
// ---------------------------------------------------------------------------
#define XAP 136
#define WFP 68
__global__ void __launch_bounds__(256) kA(
    const float* __restrict__ x,
    const float* __restrict__ Wf,  const float* __restrict__ bf,
    const float* __restrict__ Wm1, const float* __restrict__ bm1,
    const float* __restrict__ Wm2, const float* __restrict__ bm2)
{
    extern __shared__ float sa[];
    float* Xs  = sa;                 // [64][136]
    float* Wfs = Xs + CIN*XAP;       // [64][68]
    float* wms = Wfs + COUTC*WFP;    // [4][64]

    const int tid = threadIdx.x;
    const int t = blockIdx.x;
    const int n = blockIdx.y;

    for (int e = tid; e < CIN*VV; e += 256) {
        int c = e >> 7, v = e & 127;
        Xs[c*XAP + v] = x[(((size_t)n*CIN + c)*TT + t)*VV + v];
    }
    for (int e = tid; e < COUTC*CIN; e += 256) {
        int o = e >> 6, c = e & 63;
        Wfs[o*WFP + c] = Wf[e];
    }
    if (tid < 128) wms[tid] = Wm1[tid];
    else           wms[128 + (tid-128)] = Wm2[tid-128];
    __syncthreads();

    // a/b: thread v computes both r for Wm1 and Wm2
    if (tid < 128) {
        const int v = tid;
        float s[4] = {0.f, 0.f, 0.f, 0.f};
        #pragma unroll
        for (int c = 0; c < CIN; c++) {
            float xc = Xs[c*XAP + v];
            s[0] += wms[c]       * xc;
            s[1] += wms[64 + c]  * xc;
            s[2] += wms[128 + c] * xc;
            s[3] += wms[192 + c] * xc;
        }
        g_a[((size_t)n*KK + t)*VV + v]      = s[0] + __ldg(&bm1[0]);
        g_a[((size_t)n*KK + 64 + t)*VV + v] = s[1] + __ldg(&bm1[1]);
        g_b[((size_t)n*KK + t)*VV + v]      = s[2] + __ldg(&bm2[0]);
        g_b[((size_t)n*KK + 64 + t)*VV + v] = s[3] + __ldg(&bm2[1]);
    }

    // xf MMA: M=64(o) N=128(v) K=64(c)
    const int warp = tid >> 5, lane = tid & 31;
    const int grp = lane >> 2, tig = lane & 3;
    const int mg = warp & 3;          // o tile: o0 = mg*16
    const int n0 = (warp >> 2) * 64;  // v base

    float acc[8][4];
    #pragma unroll
    for (int j = 0; j < 8; j++)
        #pragma unroll
        for (int q = 0; q < 4; q++) acc[j][q] = 0.0f;

    const int r0 = mg*16 + grp;
    #pragma unroll
    for (int ks = 0; ks < 8; ks++) {
        const int k0 = ks * 8;
        uint32 a0 = to_tf32u(Wfs[r0*WFP + k0 + tig]);
        uint32 a1 = to_tf32u(Wfs[(r0+8)*WFP + k0 + tig]);
        uint32 a2 = to_tf32u(Wfs[r0*WFP + k0 + tig + 4]);
        uint32 a3 = to_tf32u(Wfs[(r0+8)*WFP + k0 + tig + 4]);
        #pragma unroll
        for (int j = 0; j < 8; j++) {
            const int vcol = n0 + j*8 + grp;
            uint32 b0 = to_tf32u(Xs[(k0+tig)*XAP + vcol]);
            uint32 b1 = to_tf32u(Xs[(k0+tig+4)*XAP + vcol]);
            mma_tf32(acc[j], a0, a1, a2, a3, b0, b1);
        }
    }

    const int c_lo = mg*16 + grp, c_hi = c_lo + 8;
    const float bf_lo = __ldg(&bf[c_lo]);
    const float bf_hi = __ldg(&bf[c_hi]);
    #pragma unroll
    for (int j = 0; j < 8; j++) {
        const int v = n0 + j*8 + 2*tig;
        *(float2*)&g_xf[(((size_t)n*COUTC + c_lo)*TT + t)*VV + v] =
            make_float2(acc[j][0] + bf_lo, acc[j][1] + bf_lo);
        *(float2*)&g_xf[(((size_t)n*COUTC + c_hi)*TT + t)*VV + v] =
            make_float2(acc[j][2] + bf_hi, acc[j][3] + bf_hi);
    }
}

// ---------------------------------------------------------------------------
// kB (unchanged from R6): xm = brm + A + Wrm @ tanh(a-b), tf32 mma inline.
// ---------------------------------------------------------------------------
#define BSMP 136
__global__ void __launch_bounds__(256, 2) kB(
    const float* __restrict__ A, const float* __restrict__ brm)
{
    extern __shared__ float sm[];
    float* bsm = sm;                // [128][136]
    float* ash = bsm + KK*BSMP;     // [128][2]
    float* wfs = ash + KK*2;        // [4][16][32][4]

    const int tid = threadIdx.x;
    const int n  = blockIdx.y;
    const int v0 = blockIdx.x * 2;

    for (int e = tid; e < KK*VV; e += 256) {
        int k = e >> 7, w = e & 127;
        bsm[k*BSMP + w] = g_b[(size_t)n*KK*VV + e];
    }
    ash[tid] = g_a[((size_t)n*KK + (tid >> 1))*VV + v0 + (tid & 1)];
    for (int e = tid; e < 8192; e += 256) wfs[e] = g_WrmF[e];
    __syncthreads();

    const int warp = tid >> 5, lane = tid & 31;
    const int grp = lane >> 2, tig = lane & 3;
    const int vbit = warp >> 2;
    const int cb = (warp & 3) * 32;

    int wc0 = cb + grp;

    float acc[4][4][4];
    #pragma unroll
    for (int m = 0; m < 4; m++)
        #pragma unroll
        for (int j = 0; j < 4; j++)
            #pragma unroll
            for (int q = 0; q < 4; q++) acc[m][j][q] = 0.0f;

    #pragma unroll 1
    for (int ks = 0; ks < 16; ks++) {
        const int k0 = ks * 8;
        const float a_lo = ash[(k0 + tig)*2 + vbit];
        const float a_hi = ash[(k0 + tig + 4)*2 + vbit];

        uint32 af[4][4];
        #pragma unroll
        for (int mg = 0; mg < 4; mg++) {
            float4 f = *(const float4*)&wfs[((mg*16 + ks)*32 + lane)*4];
            af[mg][0] = __float_as_uint(f.x);
            af[mg][1] = __float_as_uint(f.y);
            af[mg][2] = __float_as_uint(f.z);
            af[mg][3] = __float_as_uint(f.w);
        }

        const float* blo = &bsm[(k0 + tig)*BSMP];
        const float* bhi = &bsm[(k0 + tig + 4)*BSMP];
        #pragma unroll
        for (int j = 0; j < 4; j++) {
            const int wcj = wc0 + j*8;
            uint32 u0 = to_tf32(fast_tanh(a_lo - blo[wcj]));
            uint32 u1 = to_tf32(fast_tanh(a_hi - bhi[wcj]));
            #pragma unroll
            for (int mg = 0; mg < 4; mg++)
                mma_tf32(acc[mg][j], af[mg][0], af[mg][1], af[mg][2], af[mg][3], u0, u1);
        }
    }

    const int v = v0 + vbit;
    #pragma unroll
    for (int mg = 0; mg < 4; mg++) {
        const int t_lo = mg*16 + grp, t_hi = t_lo + 8;
        const float bt0 = __ldg(&brm[t_lo]);
        const float bt1 = __ldg(&brm[t_hi]);
        #pragma unroll
        for (int j = 0; j < 4; j++) {
            const int w = cb + j*8 + 2*tig;
            float2 A0 = *(const float2*)&A[((size_t)t_lo*VV + v)*VV + w];
            float2 A1 = *(const float2*)&A[((size_t)t_hi*VV + v)*VV + w];
            float2 r0, r1;
            r0.x = acc[mg][j][0] + bt0 + A0.x;  r0.y = acc[mg][j][1] + bt0 + A0.y;
            r1.x = acc[mg][j][2] + bt1 + A1.x;  r1.y = acc[mg][j][3] + bt1 + A1.y;
            *(float2*)&g_xm[(((size_t)n*TT + t_lo)*VV + v)*VV + w] = r0;
            *(float2*)&g_xm[(((size_t)n*TT + t_hi)*VV + v)*VV + w] = r1;
        }
    }
}

// ---------------------------------------------------------------------------
// kC (tf32 mma + cp.async pipeline): out = xf(64x128v) @ xm(128v x 128w)
// v chunked by 32, 2-stage cp.async double buffer.
// smem: xfs [2][64][40] + xms [2][32][136] = 55296 B
// ---------------------------------------------------------------------------
#define FCP 40
#define MCP 136
__global__ void __launch_bounds__(256) kC(float* __restrict__ out) {
    extern __shared__ float sc[];
    float* xfs = sc;                 // [2][64][40]
    float* xms = sc + 2*COUTC*FCP;   // [2][32][136]

    const int tid = threadIdx.x;
    const int t = blockIdx.x;
    const int n = blockIdx.y;

    const float* xf_base = &g_xf[(((size_t)n*COUTC)*TT + t)*VV];  // + c*TT*VV + v
    const float* xm_base = &g_xm[(((size_t)n*TT + t)*VV)*VV];     // + v*VV + w

    // stage loader: chunk ch -> buffer s
    auto load_chunk = [&](int ch, int s) {
        const int v0 = ch * 32;
        // xf: 64 rows x 32 floats = 512 x cp16 over 256 threads
        #pragma unroll
        for (int r = 0; r < 2; r++) {
            int e = tid + r*256;
            int c = e >> 3, seg = e & 7;
            cp_async16(&xfs[(s*COUTC + c)*FCP + seg*4],
                       xf_base + (size_t)c*TT*VV + v0 + seg*4);
        }
        // xm: 32 rows x 128 floats = 1024 x cp16
        #pragma unroll
        for (int r = 0; r < 4; r++) {
            int e = tid + r*256;
            int vv = e >> 5, seg = e & 31;
            cp_async16(&xms[(s*32 + vv)*MCP + seg*4],
                       xm_base + (size_t)(v0 + vv)*VV + seg*4);
        }
    };

    const int warp = tid >> 5, lane = tid & 31;
    const int grp = lane >> 2, tig = lane & 3;
    const int mg = warp & 3;          // c tile: c0 = mg*16
    const int n0 = (warp >> 2) * 64;  // w base

    float acc[8][4];
    #pragma unroll
    for (int j = 0; j < 8; j++)
        #pragma unroll
        for (int q = 0; q < 4; q++) acc[j][q] = 0.0f;

    load_chunk(0, 0);
    cp_commit();

    const int r0 = mg*16 + grp;
    #pragma unroll 1
    for (int ch = 0; ch < 4; ch++) {
        const int s = ch & 1;
        if (ch < 3) { load_chunk(ch+1, s^1); cp_commit(); }
        if (ch < 3) cp_wait<1>(); else cp_wait<0>();
        __syncthreads();

        const float* xfc = &xfs[s*COUTC*FCP];
        const float* xmc = &xms[s*32*MCP];
        #pragma unroll
        for (int ks = 0; ks < 4; ks++) {
            const int k0 = ks * 8;
            uint32 a0 = to_tf32u(xfc[r0*FCP + k0 + tig]);
            uint32 a1 = to_tf32u(xfc[(r0+8)*FCP + k0 + tig]);
            uint32 a2 = to_tf32u(xfc[r0*FCP + k0 + tig + 4]);
            uint32 a3 = to_tf32u(xfc[(r0+8)*FCP + k0 + tig + 4]);
            #pragma unroll
            for (int j = 0; j < 8; j++) {
                const int wcol = n0 + j*8 + grp;
                uint32 b0 = to_tf32u(xmc[(k0+tig)*MCP + wcol]);
                uint32 b1 = to_tf32u(xmc[(k0+tig+4)*MCP + wcol]);
                mma_tf32(acc[j], a0, a1, a2, a3, b0, b1);
            }
        }
        __syncthreads();   // compute done before next load overwrites buffer s
    }

    const int c_lo = mg*16 + grp, c_hi = c_lo + 8;
    #pragma unroll
    for (int j = 0; j < 8; j++) {
        const int w = n0 + j*8 + 2*tig;
        *(float2*)&out[(((size_t)n*COUTC + c_lo)*TT + t)*VV + w] =
            make_float2(acc[j][0], acc[j][1]);
        *(float2*)&out[(((size_t)n*COUTC + c_hi)*TT + t)*VV + w] =
            make_float2(acc[j][2], acc[j][3]);
    }
}

// ---------------------------------------------------------------------------
extern "C" void kernel_launch(void* const* d_in, const int* in_sizes, int n_in,
                              void* d_out, int out_size)
{
    const float* x   = (const float*)d_in[0];
    const float* A   = (const float*)d_in[1];
    const float* Wf  = (const float*)d_in[2];
    const float* bf  = (const float*)d_in[3];
    const float* Wm1 = (const float*)d_in[4];
    const float* bm1 = (const float*)d_in[5];
    const float* Wm2 = (const float*)d_in[6];
    const float* bm2 = (const float*)d_in[7];
    const float* Wrm = (const float*)d_in[8];
    const float* brm = (const float*)d_in[9];
    float* out = (float*)d_out;

    const int ka_smem = (CIN*XAP + COUTC*WFP + 4*64) * (int)sizeof(float);   // 53760
    const int kb_smem = (KK*BSMP + KK*2 + 8192) * (int)sizeof(float);        // 103424
    const int kc_smem = (2*COUTC*FCP + 2*32*MCP) * (int)sizeof(float);       // 55296
    static int attr_set = 0;
    if (!attr_set) {
        cudaFuncSetAttribute(kA, cudaFuncAttributeMaxDynamicSharedMemorySize, ka_smem);
        cudaFuncSetAttribute(kB, cudaFuncAttributeMaxDynamicSharedMemorySize, kb_smem);
        cudaFuncSetAttribute(kC, cudaFuncAttributeMaxDynamicSharedMemorySize, kc_smem);
        attr_set = 1;
    }

    kP<<<8, 256>>>(Wrm);
    kA<<<dim3(TT, NN), 256, ka_smem>>>(x, Wf, bf, Wm1, bm1, Wm2, bm2);
    kB<<<dim3(VV/2, NN), 256, kb_smem>>>(A, brm);
    kC<<<dim3(TT, NN), 256, kc_smem>>>(out);
}

// round 10
// speedup vs baseline: 3.0133x; 1.4324x over previous
#include <cuda_runtime.h>
#include <cstdint>

// Problem constants
#define NN    32
#define CIN   64
#define COUTC 64
#define REDC  2
#define TT    64
#define VV    128
#define KK    (REDC*TT)   // 128

typedef unsigned int uint32;

// Scratch (device globals; no allocation allowed)
__device__ float g_xf[NN*COUTC*TT*VV];      // [n][o][t][v]  67 MB
__device__ float g_a [NN*KK*VV];            // [n][k][v]      2 MB
__device__ float g_b [NN*KK*VV];            // [n][k][w]      2 MB
__device__ float g_xm[(size_t)NN*TT*VV*VV]; // [n][t][v][w] 134 MB
__device__ float g_WrmF[4*16*32*4];         // tf32 A-fragments [mg][kt][lane][4]

// tanh(x) = 1 - 2/(1+e^{2x}) via MUFU.EX2 + MUFU.RCP (abs err ~1e-6)
__device__ __forceinline__ float fast_tanh(float x) {
    float e;
    asm("ex2.approx.f32 %0, %1;" : "=f"(e) : "f"(x * 2.885390081777927f));
    float r;
    asm("rcp.approx.f32 %0, %1;" : "=f"(r) : "f"(e + 1.0f));
    return 1.0f - 2.0f * r;
}

__device__ __forceinline__ uint32 to_tf32(float x) {
    uint32 u;
    asm("cvt.rna.tf32.f32 %0, %1;" : "=r"(u) : "f"(x));
    return u;
}
__device__ __forceinline__ float tf32f(float x) {
    return __uint_as_float(to_tf32(x));
}
__device__ __forceinline__ uint32 to_tf32u(float x) { return to_tf32(x); }

__device__ __forceinline__ void mma_tf32(
    float* c,
    uint32 a0, uint32 a1, uint32 a2, uint32 a3,
    uint32 b0, uint32 b1)
{
    asm volatile(
        "mma.sync.aligned.m16n8k8.row.col.f32.tf32.tf32.f32 "
        "{%0,%1,%2,%3}, {%4,%5,%6,%7}, {%8,%9}, {%0,%1,%2,%3};"
        : "+f"(c[0]), "+f"(c[1]), "+f"(c[2]), "+f"(c[3])
        : "r"(a0), "r"(a1), "r"(a2), "r"(a3), "r"(b0), "r"(b1));
}

__device__ __forceinline__ void cp_async16(void* smem_dst, const void* gmem_src) {
    uint32 d = (uint32)__cvta_generic_to_shared(smem_dst);
    asm volatile("cp.async.cg.shared.global [%0], [%1], 16;" :: "r"(d), "l"(gmem_src));
}
__device__ __forceinline__ void cp_async8(void* smem_dst, const void* gmem_src) {
    uint32 d = (uint32)__cvta_generic_to_shared(smem_dst);
    asm volatile("cp.async.ca.shared.global [%0], [%1], 8;" :: "r"(d), "l"(gmem_src));
}
__device__ __forceinline__ void cp_commit() {
    asm volatile("cp.async.commit_group;");
}
template<int N>
__device__ __forceinline__ void cp_wait() {
    asm volatile("cp.async.wait_group %0;" :: "n"(N));
}

// ---------------------------------------------------------------------------
// kP: build tf32 A-fragments of Wrm for mma.m16n8k8.
// ---------------------------------------------------------------------------
__global__ void kP(const float* __restrict__ Wrm) {
    int idx = blockIdx.x * blockDim.x + threadIdx.x;   // 2048
    if (idx >= 2048) return;
    int lane = idx & 31, kt = (idx >> 5) & 15, mg = idx >> 9;
    int grp = lane >> 2, tig = lane & 3;
    int r0 = mg*16 + grp, r1 = r0 + 8;
    int c0 = kt*8 + tig, c1 = c0 + 4;
    float4 f;
    f.x = tf32f(Wrm[r0*KK + c0]);
    f.y = tf32f(Wrm[r1*KK + c0]);
    f.z = tf32f(Wrm[r0*KK + c1]);
    f.w = tf32f(Wrm[r1*KK + c1]);
    *(float4*)&g_WrmF[idx*4] = f;
}

// ---------------------------------------------------------------------------
// kA (tf32 mma, cp.async staging): xf = Wf @ X + bf; a,b scalar minis.
// smem: Xs [64c][136] + Wfs [64o][68] + wms [4][64]
// ---------------------------------------------------------------------------
#define XAP 136
#define WFP 68
__global__ void __launch_bounds__(256) kA(
    const float* __restrict__ x,
    const float* __restrict__ Wf,  const float* __restrict__ bf,
    const float* __restrict__ Wm1, const float* __restrict__ bm1,
    const float* __restrict__ Wm2, const float* __restrict__ bm2)
{
    extern __shared__ float sa[];
    float* Xs  = sa;                 // [64][136]
    float* Wfs = Xs + CIN*XAP;       // [64][68]
    float* wms = Wfs + COUTC*WFP;    // [4][64]

    const int tid = threadIdx.x;
    const int t = blockIdx.x;
    const int n = blockIdx.y;

    // Xs: 64 rows x 128 floats = 2048 cp16
    const float* xb = &x[(((size_t)n*CIN)*TT + t)*VV];
    #pragma unroll
    for (int r = 0; r < 8; r++) {
        int e = tid + r*256;
        int c = e >> 5, seg = e & 31;
        cp_async16(&Xs[c*XAP + seg*4], xb + (size_t)c*TT*VV + seg*4);
    }
    // Wfs: 64 rows x 64 floats = 1024 cp16
    #pragma unroll
    for (int r = 0; r < 4; r++) {
        int e = tid + r*256;
        int o = e >> 4, seg = e & 15;
        cp_async16(&Wfs[o*WFP + seg*4], Wf + o*CIN + seg*4);
    }
    // wms: 256 floats = 64 cp16 (Wm1 then Wm2, each 128 floats contiguous)
    if (tid < 32) cp_async16(&wms[tid*4], Wm1 + tid*4);
    else if (tid < 64) cp_async16(&wms[128 + (tid-32)*4], Wm2 + (tid-32)*4);
    cp_commit();
    cp_wait<0>();
    __syncthreads();

    // a/b: thread v computes both r for Wm1 and Wm2
    if (tid < 128) {
        const int v = tid;
        float s[4] = {0.f, 0.f, 0.f, 0.f};
        #pragma unroll
        for (int c = 0; c < CIN; c++) {
            float xc = Xs[c*XAP + v];
            s[0] += wms[c]       * xc;
            s[1] += wms[64 + c]  * xc;
            s[2] += wms[128 + c] * xc;
            s[3] += wms[192 + c] * xc;
        }
        g_a[((size_t)n*KK + t)*VV + v]      = s[0] + __ldg(&bm1[0]);
        g_a[((size_t)n*KK + 64 + t)*VV + v] = s[1] + __ldg(&bm1[1]);
        g_b[((size_t)n*KK + t)*VV + v]      = s[2] + __ldg(&bm2[0]);
        g_b[((size_t)n*KK + 64 + t)*VV + v] = s[3] + __ldg(&bm2[1]);
    }

    // xf MMA: M=64(o) N=128(v) K=64(c)
    const int warp = tid >> 5, lane = tid & 31;
    const int grp = lane >> 2, tig = lane & 3;
    const int mg = warp & 3;          // o tile: o0 = mg*16
    const int n0 = (warp >> 2) * 64;  // v base

    float acc[8][4];
    #pragma unroll
    for (int j = 0; j < 8; j++)
        #pragma unroll
        for (int q = 0; q < 4; q++) acc[j][q] = 0.0f;

    const int r0 = mg*16 + grp;
    #pragma unroll
    for (int ks = 0; ks < 8; ks++) {
        const int k0 = ks * 8;
        uint32 a0 = to_tf32u(Wfs[r0*WFP + k0 + tig]);
        uint32 a1 = to_tf32u(Wfs[(r0+8)*WFP + k0 + tig]);
        uint32 a2 = to_tf32u(Wfs[r0*WFP + k0 + tig + 4]);
        uint32 a3 = to_tf32u(Wfs[(r0+8)*WFP + k0 + tig + 4]);
        #pragma unroll
        for (int j = 0; j < 8; j++) {
            const int vcol = n0 + j*8 + grp;
            uint32 b0 = to_tf32u(Xs[(k0+tig)*XAP + vcol]);
            uint32 b1 = to_tf32u(Xs[(k0+tig+4)*XAP + vcol]);
            mma_tf32(acc[j], a0, a1, a2, a3, b0, b1);
        }
    }

    const int c_lo = mg*16 + grp, c_hi = c_lo + 8;
    const float bf_lo = __ldg(&bf[c_lo]);
    const float bf_hi = __ldg(&bf[c_hi]);
    #pragma unroll
    for (int j = 0; j < 8; j++) {
        const int v = n0 + j*8 + 2*tig;
        *(float2*)&g_xf[(((size_t)n*COUTC + c_lo)*TT + t)*VV + v] =
            make_float2(acc[j][0] + bf_lo, acc[j][1] + bf_lo);
        *(float2*)&g_xf[(((size_t)n*COUTC + c_hi)*TT + t)*VV + v] =
            make_float2(acc[j][2] + bf_hi, acc[j][3] + bf_hi);
    }
}

// ---------------------------------------------------------------------------
// kB: xm = brm + A + Wrm @ tanh(a-b), tf32 mma, tanh inline in B-frag layout.
// cp.async staging; ks loop unrolled x2 for cross-iteration pipelining.
// smem: bsm [128][136] + ash [128][2] + wfs 32KB = 101 KB
// ---------------------------------------------------------------------------
#define BSMP 136
__global__ void __launch_bounds__(256, 2) kB(
    const float* __restrict__ A, const float* __restrict__ brm)
{
    extern __shared__ float sm[];
    float* bsm = sm;                // [128][136]
    float* ash = bsm + KK*BSMP;     // [128][2]
    float* wfs = ash + KK*2;        // [4][16][32][4]

    const int tid = threadIdx.x;
    const int n  = blockIdx.y;
    const int v0 = blockIdx.x * 2;

    // bsm: 128 rows x 128 floats = 4096 cp16
    const float* gb = &g_b[(size_t)n*KK*VV];
    #pragma unroll
    for (int r = 0; r < 16; r++) {
        int e = tid + r*256;
        int k = e >> 5, seg = e & 31;
        cp_async16(&bsm[k*BSMP + seg*4], gb + (size_t)k*VV + seg*4);
    }
    // ash: 128 rows x 2 floats (contiguous pair at v0) = 128 cp8
    if (tid < 128)
        cp_async8(&ash[tid*2], &g_a[((size_t)n*KK + tid)*VV + v0]);
    // wfs: 8192 floats = 2048 cp16
    #pragma unroll
    for (int r = 0; r < 8; r++) {
        int e = tid + r*256;
        cp_async16(&wfs[e*4], &g_WrmF[e*4]);
    }
    cp_commit();
    cp_wait<0>();
    __syncthreads();

    const int warp = tid >> 5, lane = tid & 31;
    const int grp = lane >> 2, tig = lane & 3;
    const int vbit = warp >> 2;
    const int cb = (warp & 3) * 32;

    const int wc0 = cb + grp;

    float acc[4][4][4];
    #pragma unroll
    for (int m = 0; m < 4; m++)
        #pragma unroll
        for (int j = 0; j < 4; j++)
            #pragma unroll
            for (int q = 0; q < 4; q++) acc[m][j][q] = 0.0f;

    #pragma unroll 2
    for (int ks = 0; ks < 16; ks++) {
        const int k0 = ks * 8;
        const float a_lo = ash[(k0 + tig)*2 + vbit];
        const float a_hi = ash[(k0 + tig + 4)*2 + vbit];

        uint32 af[4][4];
        #pragma unroll
        for (int mg = 0; mg < 4; mg++) {
            float4 f = *(const float4*)&wfs[((mg*16 + ks)*32 + lane)*4];
            af[mg][0] = __float_as_uint(f.x);
            af[mg][1] = __float_as_uint(f.y);
            af[mg][2] = __float_as_uint(f.z);
            af[mg][3] = __float_as_uint(f.w);
        }

        const float* blo = &bsm[(k0 + tig)*BSMP];
        const float* bhi = &bsm[(k0 + tig + 4)*BSMP];
        #pragma unroll
        for (int j = 0; j < 4; j++) {
            const int wcj = wc0 + j*8;
            uint32 u0 = to_tf32(fast_tanh(a_lo - blo[wcj]));
            uint32 u1 = to_tf32(fast_tanh(a_hi - bhi[wcj]));
            #pragma unroll
            for (int mg = 0; mg < 4; mg++)
                mma_tf32(acc[mg][j], af[mg][0], af[mg][1], af[mg][2], af[mg][3], u0, u1);
        }
    }

    const int v = v0 + vbit;
    #pragma unroll
    for (int mg = 0; mg < 4; mg++) {
        const int t_lo = mg*16 + grp, t_hi = t_lo + 8;
        const float bt0 = __ldg(&brm[t_lo]);
        const float bt1 = __ldg(&brm[t_hi]);
        #pragma unroll
        for (int j = 0; j < 4; j++) {
            const int w = cb + j*8 + 2*tig;
            float2 A0 = *(const float2*)&A[((size_t)t_lo*VV + v)*VV + w];
            float2 A1 = *(const float2*)&A[((size_t)t_hi*VV + v)*VV + w];
            float2 r0, r1;
            r0.x = acc[mg][j][0] + bt0 + A0.x;  r0.y = acc[mg][j][1] + bt0 + A0.y;
            r1.x = acc[mg][j][2] + bt1 + A1.x;  r1.y = acc[mg][j][3] + bt1 + A1.y;
            *(float2*)&g_xm[(((size_t)n*TT + t_lo)*VV + v)*VV + w] = r0;
            *(float2*)&g_xm[(((size_t)n*TT + t_hi)*VV + v)*VV + w] = r1;
        }
    }
}

// ---------------------------------------------------------------------------
// kC (tf32 mma + cp.async pipeline): out = xf(64x128v) @ xm(128v x 128w)
// ---------------------------------------------------------------------------
#define FCP 40
#define MCP 136
__global__ void __launch_bounds__(256) kC(float* __restrict__ out) {
    extern __shared__ float sc[];
    float* xfs = sc;                 // [2][64][40]
    float* xms = sc + 2*COUTC*FCP;   // [2][32][136]

    const int tid = threadIdx.x;
    const int t = blockIdx.x;
    const int n = blockIdx.y;

    const float* xf_base = &g_xf[(((size_t)n*COUTC)*TT + t)*VV];
    const float* xm_base = &g_xm[(((size_t)n*TT + t)*VV)*VV];

    auto load_chunk = [&](int ch, int s) {
        const int v0 = ch * 32;
        #pragma unroll
        for (int r = 0; r < 2; r++) {
            int e = tid + r*256;
            int c = e >> 3, seg = e & 7;
            cp_async16(&xfs[(s*COUTC + c)*FCP + seg*4],
                       xf_base + (size_t)c*TT*VV + v0 + seg*4);
        }
        #pragma unroll
        for (int r = 0; r < 4; r++) {
            int e = tid + r*256;
            int vv = e >> 5, seg = e & 31;
            cp_async16(&xms[(s*32 + vv)*MCP + seg*4],
                       xm_base + (size_t)(v0 + vv)*VV + seg*4);
        }
    };

    const int warp = tid >> 5, lane = tid & 31;
    const int grp = lane >> 2, tig = lane & 3;
    const int mg = warp & 3;
    const int n0 = (warp >> 2) * 64;

    float acc[8][4];
    #pragma unroll
    for (int j = 0; j < 8; j++)
        #pragma unroll
        for (int q = 0; q < 4; q++) acc[j][q] = 0.0f;

    load_chunk(0, 0);
    cp_commit();

    const int r0 = mg*16 + grp;
    #pragma unroll 1
    for (int ch = 0; ch < 4; ch++) {
        const int s = ch & 1;
        if (ch < 3) { load_chunk(ch+1, s^1); cp_commit(); }
        if (ch < 3) cp_wait<1>(); else cp_wait<0>();
        __syncthreads();

        const float* xfc = &xfs[s*COUTC*FCP];
        const float* xmc = &xms[s*32*MCP];
        #pragma unroll
        for (int ks = 0; ks < 4; ks++) {
            const int k0 = ks * 8;
            uint32 a0 = to_tf32u(xfc[r0*FCP + k0 + tig]);
            uint32 a1 = to_tf32u(xfc[(r0+8)*FCP + k0 + tig]);
            uint32 a2 = to_tf32u(xfc[r0*FCP + k0 + tig + 4]);
            uint32 a3 = to_tf32u(xfc[(r0+8)*FCP + k0 + tig + 4]);
            #pragma unroll
            for (int j = 0; j < 8; j++) {
                const int wcol = n0 + j*8 + grp;
                uint32 b0 = to_tf32u(xmc[(k0+tig)*MCP + wcol]);
                uint32 b1 = to_tf32u(xmc[(k0+tig+4)*MCP + wcol]);
                mma_tf32(acc[j], a0, a1, a2, a3, b0, b1);
            }
        }
        __syncthreads();
    }

    const int c_lo = mg*16 + grp, c_hi = c_lo + 8;
    #pragma unroll
    for (int j = 0; j < 8; j++) {
        const int w = n0 + j*8 + 2*tig;
        *(float2*)&out[(((size_t)n*COUTC + c_lo)*TT + t)*VV + w] =
            make_float2(acc[j][0], acc[j][1]);
        *(float2*)&out[(((size_t)n*COUTC + c_hi)*TT + t)*VV + w] =
            make_float2(acc[j][2], acc[j][3]);
    }
}

// ---------------------------------------------------------------------------
extern "C" void kernel_launch(void* const* d_in, const int* in_sizes, int n_in,
                              void* d_out, int out_size)
{
    const float* x   = (const float*)d_in[0];
    const float* A   = (const float*)d_in[1];
    const float* Wf  = (const float*)d_in[2];
    const float* bf  = (const float*)d_in[3];
    const float* Wm1 = (const float*)d_in[4];
    const float* bm1 = (const float*)d_in[5];
    const float* Wm2 = (const float*)d_in[6];
    const float* bm2 = (const float*)d_in[7];
    const float* Wrm = (const float*)d_in[8];
    const float* brm = (const float*)d_in[9];
    float* out = (float*)d_out;

    const int ka_smem = (CIN*XAP + COUTC*WFP + 4*64) * (int)sizeof(float);   // 53760
    const int kb_smem = (KK*BSMP + KK*2 + 8192) * (int)sizeof(float);        // 103424
    const int kc_smem = (2*COUTC*FCP + 2*32*MCP) * (int)sizeof(float);       // 55296
    static int attr_set = 0;
    if (!attr_set) {
        cudaFuncSetAttribute(kA, cudaFuncAttributeMaxDynamicSharedMemorySize, ka_smem);
        cudaFuncSetAttribute(kB, cudaFuncAttributeMaxDynamicSharedMemorySize, kb_smem);
        cudaFuncSetAttribute(kC, cudaFuncAttributeMaxDynamicSharedMemorySize, kc_smem);
        attr_set = 1;
    }

    kP<<<8, 256>>>(Wrm);
    kA<<<dim3(TT, NN), 256, ka_smem>>>(x, Wf, bf, Wm1, bm1, Wm2, bm2);
    kB<<<dim3(VV/2, NN), 256, kb_smem>>>(A, brm);
    kC<<<dim3(TT, NN), 256, kc_smem>>>(out);
}

// round 11
// speedup vs baseline: 3.2259x; 1.0706x over previous
#include <cuda_runtime.h>
#include <cstdint>

// Problem constants
#define NN    32
#define CIN   64
#define COUTC 64
#define REDC  2
#define TT    64
#define VV    128
#define KK    (REDC*TT)   // 128

typedef unsigned int uint32;

// Scratch (device globals; no allocation allowed)
__device__ float g_xf[NN*COUTC*TT*VV];      // [n][o][t][v]  67 MB
__device__ float g_a [NN*KK*VV];            // [n][k][v]      2 MB
__device__ float g_b [NN*KK*VV];            // [n][k][w]      2 MB
__device__ float g_xm[(size_t)NN*TT*VV*VV]; // [n][t][v][w] 134 MB
__device__ float g_WrmF[4*16*32*4];         // tf32 A-fragments [mg][kt][lane][4]

// single-MUFU tanh (sm_75+): halves MUFU pressure vs ex2+rcp
__device__ __forceinline__ float fast_tanh(float x) {
    float y;
    asm("tanh.approx.f32 %0, %1;" : "=f"(y) : "f"(x));
    return y;
}

__device__ __forceinline__ uint32 to_tf32(float x) {
    uint32 u;
    asm("cvt.rna.tf32.f32 %0, %1;" : "=r"(u) : "f"(x));
    return u;
}
__device__ __forceinline__ float tf32f(float x) {
    return __uint_as_float(to_tf32(x));
}
__device__ __forceinline__ uint32 to_tf32u(float x) { return to_tf32(x); }

__device__ __forceinline__ void mma_tf32(
    float* c,
    uint32 a0, uint32 a1, uint32 a2, uint32 a3,
    uint32 b0, uint32 b1)
{
    asm volatile(
        "mma.sync.aligned.m16n8k8.row.col.f32.tf32.tf32.f32 "
        "{%0,%1,%2,%3}, {%4,%5,%6,%7}, {%8,%9}, {%0,%1,%2,%3};"
        : "+f"(c[0]), "+f"(c[1]), "+f"(c[2]), "+f"(c[3])
        : "r"(a0), "r"(a1), "r"(a2), "r"(a3), "r"(b0), "r"(b1));
}

__device__ __forceinline__ void cp_async16(void* smem_dst, const void* gmem_src) {
    uint32 d = (uint32)__cvta_generic_to_shared(smem_dst);
    asm volatile("cp.async.cg.shared.global [%0], [%1], 16;" :: "r"(d), "l"(gmem_src));
}
__device__ __forceinline__ void cp_async8(void* smem_dst, const void* gmem_src) {
    uint32 d = (uint32)__cvta_generic_to_shared(smem_dst);
    asm volatile("cp.async.ca.shared.global [%0], [%1], 8;" :: "r"(d), "l"(gmem_src));
}
__device__ __forceinline__ void cp_commit() {
    asm volatile("cp.async.commit_group;");
}
template<int N>
__device__ __forceinline__ void cp_wait() {
    asm volatile("cp.async.wait_group %0;" :: "n"(N));
}

// ---------------------------------------------------------------------------
// kP: build tf32 A-fragments of Wrm for mma.m16n8k8.
// ---------------------------------------------------------------------------
__global__ void kP(const float* __restrict__ Wrm) {
    int idx = blockIdx.x * blockDim.x + threadIdx.x;   // 2048
    if (idx >= 2048) return;
    int lane = idx & 31, kt = (idx >> 5) & 15, mg = idx >> 9;
    int grp = lane >> 2, tig = lane & 3;
    int r0 = mg*16 + grp, r1 = r0 + 8;
    int c0 = kt*8 + tig, c1 = c0 + 4;
    float4 f;
    f.x = tf32f(Wrm[r0*KK + c0]);
    f.y = tf32f(Wrm[r1*KK + c0]);
    f.z = tf32f(Wrm[r0*KK + c1]);
    f.w = tf32f(Wrm[r1*KK + c1]);
    *(float4*)&g_WrmF[idx*4] = f;
}

// ---------------------------------------------------------------------------
// kA (tf32 mma, cp.async staging): xf = Wf @ X + bf; a,b scalar minis.
// smem: Xs [64c][136] + Wfs [64o][68] + wms [4][64]
// ---------------------------------------------------------------------------
#define XAP 136
#define WFP 68
__global__ void __launch_bounds__(256) kA(
    const float* __restrict__ x,
    const float* __restrict__ Wf,  const float* __restrict__ bf,
    const float* __restrict__ Wm1, const float* __restrict__ bm1,
    const float* __restrict__ Wm2, const float* __restrict__ bm2)
{
    extern __shared__ float sa[];
    float* Xs  = sa;                 // [64][136]
    float* Wfs = Xs + CIN*XAP;       // [64][68]
    float* wms = Wfs + COUTC*WFP;    // [4][64]

    const int tid = threadIdx.x;
    const int t = blockIdx.x;
    const int n = blockIdx.y;

    const float* xb = &x[(((size_t)n*CIN)*TT + t)*VV];
    #pragma unroll
    for (int r = 0; r < 8; r++) {
        int e = tid + r*256;
        int c = e >> 5, seg = e & 31;
        cp_async16(&Xs[c*XAP + seg*4], xb + (size_t)c*TT*VV + seg*4);
    }
    #pragma unroll
    for (int r = 0; r < 4; r++) {
        int e = tid + r*256;
        int o = e >> 4, seg = e & 15;
        cp_async16(&Wfs[o*WFP + seg*4], Wf + o*CIN + seg*4);
    }
    if (tid < 32) cp_async16(&wms[tid*4], Wm1 + tid*4);
    else if (tid < 64) cp_async16(&wms[128 + (tid-32)*4], Wm2 + (tid-32)*4);
    cp_commit();
    cp_wait<0>();
    __syncthreads();

    if (tid < 128) {
        const int v = tid;
        float s[4] = {0.f, 0.f, 0.f, 0.f};
        #pragma unroll
        for (int c = 0; c < CIN; c++) {
            float xc = Xs[c*XAP + v];
            s[0] += wms[c]       * xc;
            s[1] += wms[64 + c]  * xc;
            s[2] += wms[128 + c] * xc;
            s[3] += wms[192 + c] * xc;
        }
        g_a[((size_t)n*KK + t)*VV + v]      = s[0] + __ldg(&bm1[0]);
        g_a[((size_t)n*KK + 64 + t)*VV + v] = s[1] + __ldg(&bm1[1]);
        g_b[((size_t)n*KK + t)*VV + v]      = s[2] + __ldg(&bm2[0]);
        g_b[((size_t)n*KK + 64 + t)*VV + v] = s[3] + __ldg(&bm2[1]);
    }

    const int warp = tid >> 5, lane = tid & 31;
    const int grp = lane >> 2, tig = lane & 3;
    const int mg = warp & 3;
    const int n0 = (warp >> 2) * 64;

    float acc[8][4];
    #pragma unroll
    for (int j = 0; j < 8; j++)
        #pragma unroll
        for (int q = 0; q < 4; q++) acc[j][q] = 0.0f;

    const int r0 = mg*16 + grp;
    #pragma unroll
    for (int ks = 0; ks < 8; ks++) {
        const int k0 = ks * 8;
        uint32 a0 = to_tf32u(Wfs[r0*WFP + k0 + tig]);
        uint32 a1 = to_tf32u(Wfs[(r0+8)*WFP + k0 + tig]);
        uint32 a2 = to_tf32u(Wfs[r0*WFP + k0 + tig + 4]);
        uint32 a3 = to_tf32u(Wfs[(r0+8)*WFP + k0 + tig + 4]);
        #pragma unroll
        for (int j = 0; j < 8; j++) {
            const int vcol = n0 + j*8 + grp;
            uint32 b0 = to_tf32u(Xs[(k0+tig)*XAP + vcol]);
            uint32 b1 = to_tf32u(Xs[(k0+tig+4)*XAP + vcol]);
            mma_tf32(acc[j], a0, a1, a2, a3, b0, b1);
        }
    }

    const int c_lo = mg*16 + grp, c_hi = c_lo + 8;
    const float bf_lo = __ldg(&bf[c_lo]);
    const float bf_hi = __ldg(&bf[c_hi]);
    #pragma unroll
    for (int j = 0; j < 8; j++) {
        const int v = n0 + j*8 + 2*tig;
        *(float2*)&g_xf[(((size_t)n*COUTC + c_lo)*TT + t)*VV + v] =
            make_float2(acc[j][0] + bf_lo, acc[j][1] + bf_lo);
        *(float2*)&g_xf[(((size_t)n*COUTC + c_hi)*TT + t)*VV + v] =
            make_float2(acc[j][2] + bf_hi, acc[j][3] + bf_hi);
    }
}

// ---------------------------------------------------------------------------
// kB: xm = brm + A + Wrm @ tanh(a-b), tf32 mma, tanh.approx inline.
// Per ks: batch all 8 tanh -> then 16 HMMA (MUFU streams, MMA streams).
// smem: bsm [128][136] + ash [128][2] + wfs 32KB = 101 KB
// ---------------------------------------------------------------------------
#define BSMP 136
__global__ void __launch_bounds__(256, 2) kB(
    const float* __restrict__ A, const float* __restrict__ brm)
{
    extern __shared__ float sm[];
    float* bsm = sm;                // [128][136]
    float* ash = bsm + KK*BSMP;     // [128][2]
    float* wfs = ash + KK*2;        // [4][16][32][4]

    const int tid = threadIdx.x;
    const int n  = blockIdx.y;
    const int v0 = blockIdx.x * 2;

    const float* gb = &g_b[(size_t)n*KK*VV];
    #pragma unroll
    for (int r = 0; r < 16; r++) {
        int e = tid + r*256;
        int k = e >> 5, seg = e & 31;
        cp_async16(&bsm[k*BSMP + seg*4], gb + (size_t)k*VV + seg*4);
    }
    if (tid < 128)
        cp_async8(&ash[tid*2], &g_a[((size_t)n*KK + tid)*VV + v0]);
    #pragma unroll
    for (int r = 0; r < 8; r++) {
        int e = tid + r*256;
        cp_async16(&wfs[e*4], &g_WrmF[e*4]);
    }
    cp_commit();
    cp_wait<0>();
    __syncthreads();

    const int warp = tid >> 5, lane = tid & 31;
    const int grp = lane >> 2, tig = lane & 3;
    const int vbit = warp >> 2;
    const int cb = (warp & 3) * 32;

    const int wc0 = cb + grp;

    float acc[4][4][4];
    #pragma unroll
    for (int m = 0; m < 4; m++)
        #pragma unroll
        for (int j = 0; j < 4; j++)
            #pragma unroll
            for (int q = 0; q < 4; q++) acc[m][j][q] = 0.0f;

    #pragma unroll 2
    for (int ks = 0; ks < 16; ks++) {
        const int k0 = ks * 8;
        const float a_lo = ash[(k0 + tig)*2 + vbit];
        const float a_hi = ash[(k0 + tig + 4)*2 + vbit];

        const float* blo = &bsm[(k0 + tig)*BSMP];
        const float* bhi = &bsm[(k0 + tig + 4)*BSMP];

        // batch all 8 tanh first (MUFU streams back-to-back)
        uint32 u0[4], u1[4];
        #pragma unroll
        for (int j = 0; j < 4; j++) {
            const int wcj = wc0 + j*8;
            u0[j] = to_tf32(fast_tanh(a_lo - blo[wcj]));
            u1[j] = to_tf32(fast_tanh(a_hi - bhi[wcj]));
        }

        uint32 af[4][4];
        #pragma unroll
        for (int mg = 0; mg < 4; mg++) {
            float4 f = *(const float4*)&wfs[((mg*16 + ks)*32 + lane)*4];
            af[mg][0] = __float_as_uint(f.x);
            af[mg][1] = __float_as_uint(f.y);
            af[mg][2] = __float_as_uint(f.z);
            af[mg][3] = __float_as_uint(f.w);
        }

        #pragma unroll
        for (int j = 0; j < 4; j++)
            #pragma unroll
            for (int mg = 0; mg < 4; mg++)
                mma_tf32(acc[mg][j], af[mg][0], af[mg][1], af[mg][2], af[mg][3],
                         u0[j], u1[j]);
    }

    const int v = v0 + vbit;
    #pragma unroll
    for (int mg = 0; mg < 4; mg++) {
        const int t_lo = mg*16 + grp, t_hi = t_lo + 8;
        const float bt0 = __ldg(&brm[t_lo]);
        const float bt1 = __ldg(&brm[t_hi]);
        #pragma unroll
        for (int j = 0; j < 4; j++) {
            const int w = cb + j*8 + 2*tig;
            float2 A0 = *(const float2*)&A[((size_t)t_lo*VV + v)*VV + w];
            float2 A1 = *(const float2*)&A[((size_t)t_hi*VV + v)*VV + w];
            float2 r0, r1;
            r0.x = acc[mg][j][0] + bt0 + A0.x;  r0.y = acc[mg][j][1] + bt0 + A0.y;
            r1.x = acc[mg][j][2] + bt1 + A1.x;  r1.y = acc[mg][j][3] + bt1 + A1.y;
            *(float2*)&g_xm[(((size_t)n*TT + t_lo)*VV + v)*VV + w] = r0;
            *(float2*)&g_xm[(((size_t)n*TT + t_hi)*VV + v)*VV + w] = r1;
        }
    }
}

// ---------------------------------------------------------------------------
// kC (tf32 mma + cp.async pipeline): out = xf(64x128v) @ xm(128v x 128w)
// ---------------------------------------------------------------------------
#define FCP 40
#define MCP 136
__global__ void __launch_bounds__(256) kC(float* __restrict__ out) {
    extern __shared__ float sc[];
    float* xfs = sc;                 // [2][64][40]
    float* xms = sc + 2*COUTC*FCP;   // [2][32][136]

    const int tid = threadIdx.x;
    const int t = blockIdx.x;
    const int n = blockIdx.y;

    const float* xf_base = &g_xf[(((size_t)n*COUTC)*TT + t)*VV];
    const float* xm_base = &g_xm[(((size_t)n*TT + t)*VV)*VV];

    auto load_chunk = [&](int ch, int s) {
        const int v0 = ch * 32;
        #pragma unroll
        for (int r = 0; r < 2; r++) {
            int e = tid + r*256;
            int c = e >> 3, seg = e & 7;
            cp_async16(&xfs[(s*COUTC + c)*FCP + seg*4],
                       xf_base + (size_t)c*TT*VV + v0 + seg*4);
        }
        #pragma unroll
        for (int r = 0; r < 4; r++) {
            int e = tid + r*256;
            int vv = e >> 5, seg = e & 31;
            cp_async16(&xms[(s*32 + vv)*MCP + seg*4],
                       xm_base + (size_t)(v0 + vv)*VV + seg*4);
        }
    };

    const int warp = tid >> 5, lane = tid & 31;
    const int grp = lane >> 2, tig = lane & 3;
    const int mg = warp & 3;
    const int n0 = (warp >> 2) * 64;

    float acc[8][4];
    #pragma unroll
    for (int j = 0; j < 8; j++)
        #pragma unroll
        for (int q = 0; q < 4; q++) acc[j][q] = 0.0f;

    load_chunk(0, 0);
    cp_commit();

    const int r0 = mg*16 + grp;
    #pragma unroll 1
    for (int ch = 0; ch < 4; ch++) {
        const int s = ch & 1;
        if (ch < 3) { load_chunk(ch+1, s^1); cp_commit(); }
        if (ch < 3) cp_wait<1>(); else cp_wait<0>();
        __syncthreads();

        const float* xfc = &xfs[s*COUTC*FCP];
        const float* xmc = &xms[s*32*MCP];
        #pragma unroll
        for (int ks = 0; ks < 4; ks++) {
            const int k0 = ks * 8;
            uint32 a0 = to_tf32u(xfc[r0*FCP + k0 + tig]);
            uint32 a1 = to_tf32u(xfc[(r0+8)*FCP + k0 + tig]);
            uint32 a2 = to_tf32u(xfc[r0*FCP + k0 + tig + 4]);
            uint32 a3 = to_tf32u(xfc[(r0+8)*FCP + k0 + tig + 4]);
            #pragma unroll
            for (int j = 0; j < 8; j++) {
                const int wcol = n0 + j*8 + grp;
                uint32 b0 = to_tf32u(xmc[(k0+tig)*MCP + wcol]);
                uint32 b1 = to_tf32u(xmc[(k0+tig+4)*MCP + wcol]);
                mma_tf32(acc[j], a0, a1, a2, a3, b0, b1);
            }
        }
        __syncthreads();
    }

    const int c_lo = mg*16 + grp, c_hi = c_lo + 8;
    #pragma unroll
    for (int j = 0; j < 8; j++) {
        const int w = n0 + j*8 + 2*tig;
        *(float2*)&out[(((size_t)n*COUTC + c_lo)*TT + t)*VV + w] =
            make_float2(acc[j][0], acc[j][1]);
        *(float2*)&out[(((size_t)n*COUTC + c_hi)*TT + t)*VV + w] =
            make_float2(acc[j][2], acc[j][3]);
    }
}

// ---------------------------------------------------------------------------
extern "C" void kernel_launch(void* const* d_in, const int* in_sizes, int n_in,
                              void* d_out, int out_size)
{
    const float* x   = (const float*)d_in[0];
    const float* A   = (const float*)d_in[1];
    const float* Wf  = (const float*)d_in[2];
    const float* bf  = (const float*)d_in[3];
    const float* Wm1 = (const float*)d_in[4];
    const float* bm1 = (const float*)d_in[5];
    const float* Wm2 = (const float*)d_in[6];
    const float* bm2 = (const float*)d_in[7];
    const float* Wrm = (const float*)d_in[8];
    const float* brm = (const float*)d_in[9];
    float* out = (float*)d_out;

    const int ka_smem = (CIN*XAP + COUTC*WFP + 4*64) * (int)sizeof(float);   // 53760
    const int kb_smem = (KK*BSMP + KK*2 + 8192) * (int)sizeof(float);        // 103424
    const int kc_smem = (2*COUTC*FCP + 2*32*MCP) * (int)sizeof(float);       // 55296
    static int attr_set = 0;
    if (!attr_set) {
        cudaFuncSetAttribute(kA, cudaFuncAttributeMaxDynamicSharedMemorySize, ka_smem);
        cudaFuncSetAttribute(kB, cudaFuncAttributeMaxDynamicSharedMemorySize, kb_smem);
        cudaFuncSetAttribute(kC, cudaFuncAttributeMaxDynamicSharedMemorySize, kc_smem);
        attr_set = 1;
    }

    kP<<<8, 256>>>(Wrm);
    kA<<<dim3(TT, NN), 256, ka_smem>>>(x, Wf, bf, Wm1, bm1, Wm2, bm2);
    kB<<<dim3(VV/2, NN), 256, kb_smem>>>(A, brm);
    kC<<<dim3(TT, NN), 256, kc_smem>>>(out);
}